// round 5
// baseline (speedup 1.0000x reference)
#include <cuda_runtime.h>
#include <cuda_bf16.h>

// Problem constants (fixed by setup_inputs): B=8, D=1024, comp 24x24, orig 96x96,
// KERNEL=STRIDE=4, PAD=0 -> all window slots valid, non-overlapping tiling.
constexpr int B_   = 8;
constexpr int D_   = 1024;
constexpr int CH_  = 24, CW_ = 24;
constexpr int OH_  = 96, OW_ = 96;
constexpr int N_   = CH_ * CW_;       // 576 compressed tokens per batch
constexpr int NT_  = B_ * N_;         // 4608 tokens
constexpr int KER_ = 4;
constexpr int WIN_ = KER_ * KER_;     // 16 window slots
constexpr int BLKS_ = NT_ * 4;        // 18432 blocks: 4 slots per 256-thr block
constexpr float EPS_ = 1e-12f;
constexpr int NBUCK_ = 64;

// Spread accumulator buckets (256B stride: distinct L2 lines) + completion
// counter. Device globals are zero-initialized at module load; the finishing
// block resets them so each graph replay starts clean.
__device__ float        g_buck[NBUCK_ * 64];   // bucket i at g_buck[i*64]
__device__ unsigned int g_count;

__global__ __launch_bounds__(256, 4)
void rf_sim_kernel(const float* __restrict__ comp, const float* __restrict__ orig,
                   float* __restrict__ out) {
    __shared__ float s_part[8][3];   // per-warp (dot, rr, cc) partials

    const int blk   = blockIdx.x;
    const int token = blk >> 2;      // 4 blocks per token
    const int quad  = blk & 3;       // which group of 4 window slots
    const int b  = token / N_;
    const int t  = token - b * N_;
    const int Hc = t / CW_;
    const int Wc = t - Hc * CW_;

    const int tid  = threadIdx.x;
    const int w    = tid >> 5;       // 8 warps: warp = (slot_local, D-half)
    const int lane = tid & 31;
    const int slot = quad * 4 + (w >> 1);
    const int half = w & 1;          // which 512-float half of D
    const int dh   = slot >> 2;
    const int dw   = slot & 3;
    const int row  = (Hc * KER_ + dh) * OW_ + (Wc * KER_ + dw);

    const float4* r4 = reinterpret_cast<const float4*>(
        orig + ((size_t)b * (OH_ * OW_) + row) * D_ + half * 512);
    const float4* c4 = reinterpret_cast<const float4*>(
        comp + (size_t)token * D_ + half * 512);

    // Front-batch ALL loads (8 x LDG.128 per thread, 32 data regs) so the full
    // memory-level parallelism is exposed before any FMA consumes a value.
    float4 rv0 = r4[lane];      float4 rv1 = r4[lane + 32];
    float4 rv2 = r4[lane + 64]; float4 rv3 = r4[lane + 96];
    float4 cv0 = c4[lane];      float4 cv1 = c4[lane + 32];
    float4 cv2 = c4[lane + 64]; float4 cv3 = c4[lane + 96];

    float dot, rr, cc;
    dot  = rv0.x*cv0.x + rv0.y*cv0.y + rv0.z*cv0.z + rv0.w*cv0.w;
    rr   = rv0.x*rv0.x + rv0.y*rv0.y + rv0.z*rv0.z + rv0.w*rv0.w;
    cc   = cv0.x*cv0.x + cv0.y*cv0.y + cv0.z*cv0.z + cv0.w*cv0.w;
    dot += rv1.x*cv1.x + rv1.y*cv1.y + rv1.z*cv1.z + rv1.w*cv1.w;
    rr  += rv1.x*rv1.x + rv1.y*rv1.y + rv1.z*rv1.z + rv1.w*rv1.w;
    cc  += cv1.x*cv1.x + cv1.y*cv1.y + cv1.z*cv1.z + cv1.w*cv1.w;
    dot += rv2.x*cv2.x + rv2.y*cv2.y + rv2.z*cv2.z + rv2.w*cv2.w;
    rr  += rv2.x*rv2.x + rv2.y*rv2.y + rv2.z*rv2.z + rv2.w*rv2.w;
    cc  += cv2.x*cv2.x + cv2.y*cv2.y + cv2.z*cv2.z + cv2.w*cv2.w;
    dot += rv3.x*cv3.x + rv3.y*cv3.y + rv3.z*cv3.z + rv3.w*cv3.w;
    rr  += rv3.x*rv3.x + rv3.y*rv3.y + rv3.z*rv3.z + rv3.w*rv3.w;
    cc  += cv3.x*cv3.x + cv3.y*cv3.y + cv3.z*cv3.z + cv3.w*cv3.w;

    #pragma unroll
    for (int o = 16; o > 0; o >>= 1) {
        dot += __shfl_xor_sync(0xffffffffu, dot, o);
        rr  += __shfl_xor_sync(0xffffffffu, rr,  o);
        cc  += __shfl_xor_sync(0xffffffffu, cc,  o);
    }
    if (lane == 0) {
        s_part[w][0] = dot;
        s_part[w][1] = rr;
        s_part[w][2] = cc;
    }
    __syncthreads();

    if (tid == 0) {
        float s = 0.f;
        #pragma unroll
        for (int i = 0; i < 4; i++) {   // combine the two D-halves of each slot
            float d  = s_part[2*i][0] + s_part[2*i + 1][0];
            float r2 = s_part[2*i][1] + s_part[2*i + 1][1];
            float c2 = s_part[2*i][2] + s_part[2*i + 1][2];
            s += d / (fmaxf(sqrtf(c2), EPS_) * fmaxf(sqrtf(r2), EPS_));
        }
        atomicAdd(&g_buck[(blk & (NBUCK_ - 1)) * 64], s);
        __threadfence();
        unsigned prev = atomicAdd(&g_count, 1u);
        if (prev == (unsigned)(BLKS_ - 1)) {
            __threadfence();
            float tot = 0.f;
            #pragma unroll
            for (int i = 0; i < NBUCK_; i++)
                tot += *((volatile float*)&g_buck[i * 64]);
            out[0] = 1.0f - tot / (float)(NT_ * WIN_);
            // Reset for the next graph replay.
            #pragma unroll
            for (int i = 0; i < NBUCK_; i++)
                g_buck[i * 64] = 0.f;
            __threadfence();
            g_count = 0u;
        }
    }
}

extern "C" void kernel_launch(void* const* d_in, const int* in_sizes, int n_in,
                              void* d_out, int out_size) {
    const float* comp = (const float*)d_in[0];
    const float* orig = (const float*)d_in[1];
    rf_sim_kernel<<<BLKS_, 256>>>(comp, orig, (float*)d_out);
}

// round 6
// speedup vs baseline: 1.4929x; 1.4929x over previous
#include <cuda_runtime.h>
#include <cuda_bf16.h>

// Problem constants (fixed by setup_inputs): B=8, D=1024, comp 24x24, orig 96x96,
// KERNEL=STRIDE=4, PAD=0 -> all window slots valid, non-overlapping tiling.
constexpr int B_   = 8;
constexpr int D_   = 1024;
constexpr int CH_  = 24, CW_ = 24;
constexpr int OH_  = 96, OW_ = 96;
constexpr int N_   = CH_ * CW_;       // 576 compressed tokens per batch
constexpr int NT_  = B_ * N_;         // 4608 tokens
constexpr int KER_ = 4;
constexpr int WIN_ = KER_ * KER_;     // 16 window slots
constexpr int ITEMS_ = NT_ * WIN_;    // 73728 (token, slot) work items
constexpr float EPS_ = 1e-12f;

// Persistent launch shape: 760 CTAs x 8 warps, grid-stride over items.
constexpr int CTAS_  = 760;
constexpr int WPB_   = 8;             // warps per block (256 threads)
constexpr int TOTW_  = CTAS_ * WPB_;  // 6080 resident warps

constexpr int NBUCK_ = 64;

// Spread accumulator buckets (256B stride: distinct L2 lines) + completion
// counter (counts warp arrivals). Zero-initialized at module load; the
// finishing warp resets everything so each graph replay starts clean.
__device__ float        g_buck[NBUCK_ * 64];   // bucket i at g_buck[i*64]
__device__ unsigned int g_count;

__global__ __launch_bounds__(256, 5)
void rf_sim_kernel(const float* __restrict__ comp, const float* __restrict__ orig,
                   float* __restrict__ out) {
    const int tid  = threadIdx.x;
    const int lane = tid & 31;
    const int wid  = tid >> 5;
    const int gw   = blockIdx.x * WPB_ + wid;   // global warp id

    float sim_acc = 0.f;

    // Persistent warps: stream (token, slot) items back-to-back so loads stay
    // continuously in flight (no CTA churn, no barriers in the hot path).
    for (int item = gw; item < ITEMS_; item += TOTW_) {
        const int token = item >> 4;
        const int slot  = item & 15;
        const int b  = token / N_;
        const int t  = token - b * N_;
        const int Hc = t / CW_;
        const int Wc = t - Hc * CW_;
        const int dh = slot >> 2;
        const int dw = slot & 3;
        const int row = (Hc * KER_ + dh) * OW_ + (Wc * KER_ + dw);

        const float4* r4 = reinterpret_cast<const float4*>(
            orig + ((size_t)b * (OH_ * OW_) + row) * D_);
        const float4* c4 = reinterpret_cast<const float4*>(
            comp + (size_t)token * D_);

        float dot = 0.f, rr = 0.f, cc = 0.f;
        #pragma unroll
        for (int i = 0; i < 8; i++) {
            float4 r = r4[lane + i * 32];
            float4 c = c4[lane + i * 32];
            dot += r.x * c.x + r.y * c.y + r.z * c.z + r.w * c.w;
            rr  += r.x * r.x + r.y * r.y + r.z * r.z + r.w * r.w;
            cc  += c.x * c.x + c.y * c.y + c.z * c.z + c.w * c.w;
        }
        #pragma unroll
        for (int o = 16; o > 0; o >>= 1) {
            dot += __shfl_xor_sync(0xffffffffu, dot, o);
            rr  += __shfl_xor_sync(0xffffffffu, rr,  o);
            cc  += __shfl_xor_sync(0xffffffffu, cc,  o);
        }
        sim_acc += dot / (fmaxf(sqrtf(cc), EPS_) * fmaxf(sqrtf(rr), EPS_));
    }

    // One atomic per warp into a spread bucket; last warp to finish writes out.
    if (lane == 0) {
        atomicAdd(&g_buck[(gw & (NBUCK_ - 1)) * 64], sim_acc);
        __threadfence();
        unsigned prev = atomicAdd(&g_count, 1u);
        if (prev == (unsigned)(TOTW_ - 1)) {
            __threadfence();
            float tot = 0.f;
            #pragma unroll
            for (int i = 0; i < NBUCK_; i++)
                tot += *((volatile float*)&g_buck[i * 64]);
            out[0] = 1.0f - tot / (float)ITEMS_;
            // Reset for the next graph replay.
            #pragma unroll
            for (int i = 0; i < NBUCK_; i++)
                g_buck[i * 64] = 0.f;
            __threadfence();
            g_count = 0u;
        }
    }
}

extern "C" void kernel_launch(void* const* d_in, const int* in_sizes, int n_in,
                              void* d_out, int out_size) {
    const float* comp = (const float*)d_in[0];
    const float* orig = (const float*)d_in[1];
    rf_sim_kernel<<<CTAS_, 256>>>(comp, orig, (float*)d_out);
}

// round 7
// speedup vs baseline: 1.5604x; 1.0452x over previous
#include <cuda_runtime.h>
#include <cuda_bf16.h>

// Problem constants (fixed by setup_inputs): B=8, D=1024, comp 24x24, orig 96x96,
// KERNEL=STRIDE=4, PAD=0 -> all window slots valid, non-overlapping tiling.
constexpr int B_   = 8;
constexpr int D_   = 1024;
constexpr int CH_  = 24, CW_ = 24;
constexpr int OH_  = 96, OW_ = 96;
constexpr int N_   = CH_ * CW_;       // 576 compressed tokens per batch
constexpr int NT_  = B_ * N_;         // 4608 tokens
constexpr int KER_ = 4;
constexpr int WIN_ = KER_ * KER_;     // 16 window slots
constexpr int ITEMS_ = NT_ * WIN_;    // 73728 (token, slot) work items
constexpr float EPS_ = 1e-12f;

// Persistent launch: 768 CTAs x 8 warps = 6144 warps; 73728/6144 = exactly 12
// items per warp (zero tail imbalance). At occ 6 (42-reg cap) capacity is
// 148*6 = 888 CTAs -> single wave.
constexpr int CTAS_  = 768;
constexpr int WPB_   = 8;
constexpr int TOTW_  = CTAS_ * WPB_;  // 6144
constexpr int IPW_   = ITEMS_ / TOTW_; // 12

constexpr int NBUCK_ = 64;

// Spread accumulator buckets (256B stride: distinct L2 lines) + completion
// counter (counts warp arrivals). Zero-initialized at module load; the
// finishing warp resets everything so each graph replay starts clean.
__device__ float        g_buck[NBUCK_ * 64];   // bucket i at g_buck[i*64]
__device__ unsigned int g_count;

__global__ __launch_bounds__(256, 6)
void rf_sim_kernel(const float* __restrict__ comp, const float* __restrict__ orig,
                   float* __restrict__ out) {
    const int tid  = threadIdx.x;
    const int lane = tid & 31;
    const int wid  = tid >> 5;
    const int gw   = blockIdx.x * WPB_ + wid;   // global warp id

    float sim_acc = 0.f;

    // Persistent warps: each warp streams exactly IPW_ (token, slot) items so
    // loads stay continuously in flight (no CTA churn, no barriers).
    int item = gw;
    #pragma unroll 1
    for (int it = 0; it < IPW_; it++, item += TOTW_) {
        const int token = item >> 4;
        const int slot  = item & 15;
        const int b  = token / N_;
        const int t  = token - b * N_;
        const int Hc = t / CW_;
        const int Wc = t - Hc * CW_;
        const int dh = slot >> 2;
        const int dw = slot & 3;
        const int row = (Hc * KER_ + dh) * OW_ + (Wc * KER_ + dw);

        const float4* r4 = reinterpret_cast<const float4*>(
            orig + ((size_t)b * (OH_ * OW_) + row) * D_);
        const float4* c4 = reinterpret_cast<const float4*>(
            comp + (size_t)token * D_);

        float dot = 0.f, rr = 0.f, cc = 0.f;
        // Two half-D batches of 4 r + 4 c float4 loads: 32 live data regs,
        // fits the 42-reg budget (occ 6) without spills. r is stream-once ->
        // evict-first (__ldcs); c is reused 8x within the CTA -> default.
        #pragma unroll
        for (int h = 0; h < 2; h++) {
            const int base = h * 128 + lane;
            float4 r0 = __ldcs(&r4[base]);
            float4 r1 = __ldcs(&r4[base + 32]);
            float4 r2 = __ldcs(&r4[base + 64]);
            float4 r3 = __ldcs(&r4[base + 96]);
            float4 c0 = c4[base];
            float4 c1 = c4[base + 32];
            float4 c2 = c4[base + 64];
            float4 c3 = c4[base + 96];
            dot += r0.x*c0.x + r0.y*c0.y + r0.z*c0.z + r0.w*c0.w;
            rr  += r0.x*r0.x + r0.y*r0.y + r0.z*r0.z + r0.w*r0.w;
            cc  += c0.x*c0.x + c0.y*c0.y + c0.z*c0.z + c0.w*c0.w;
            dot += r1.x*c1.x + r1.y*c1.y + r1.z*c1.z + r1.w*c1.w;
            rr  += r1.x*r1.x + r1.y*r1.y + r1.z*r1.z + r1.w*r1.w;
            cc  += c1.x*c1.x + c1.y*c1.y + c1.z*c1.z + c1.w*c1.w;
            dot += r2.x*c2.x + r2.y*c2.y + r2.z*c2.z + r2.w*c2.w;
            rr  += r2.x*r2.x + r2.y*r2.y + r2.z*r2.z + r2.w*r2.w;
            cc  += c2.x*c2.x + c2.y*c2.y + c2.z*c2.z + c2.w*c2.w;
            dot += r3.x*c3.x + r3.y*c3.y + r3.z*c3.z + r3.w*c3.w;
            rr  += r3.x*r3.x + r3.y*r3.y + r3.z*r3.z + r3.w*r3.w;
            cc  += c3.x*c3.x + c3.y*c3.y + c3.z*c3.z + c3.w*c3.w;
        }
        #pragma unroll
        for (int o = 16; o > 0; o >>= 1) {
            dot += __shfl_xor_sync(0xffffffffu, dot, o);
            rr  += __shfl_xor_sync(0xffffffffu, rr,  o);
            cc  += __shfl_xor_sync(0xffffffffu, cc,  o);
        }
        sim_acc += dot / (fmaxf(sqrtf(cc), EPS_) * fmaxf(sqrtf(rr), EPS_));
    }

    // One atomic per warp into a spread bucket; last warp to finish writes out.
    if (lane == 0) {
        atomicAdd(&g_buck[(gw & (NBUCK_ - 1)) * 64], sim_acc);
        __threadfence();
        unsigned prev = atomicAdd(&g_count, 1u);
        if (prev == (unsigned)(TOTW_ - 1)) {
            __threadfence();
            float tot = 0.f;
            #pragma unroll
            for (int i = 0; i < NBUCK_; i++)
                tot += *((volatile float*)&g_buck[i * 64]);
            out[0] = 1.0f - tot / (float)ITEMS_;
            // Reset for the next graph replay.
            #pragma unroll
            for (int i = 0; i < NBUCK_; i++)
                g_buck[i * 64] = 0.f;
            __threadfence();
            g_count = 0u;
        }
    }
}

extern "C" void kernel_launch(void* const* d_in, const int* in_sizes, int n_in,
                              void* d_out, int out_size) {
    const float* comp = (const float*)d_in[0];
    const float* orig = (const float*)d_in[1];
    rf_sim_kernel<<<CTAS_, 256>>>(comp, orig, (float*)d_out);
}